// round 6
// baseline (speedup 1.0000x reference)
#include <cuda_runtime.h>
#include <cstdint>
#include <math.h>

#define N_HEADS 16
#define HIDDEN  1024
#define HS      64
#define BATCH   2
#define SEQ     2048
#define M_ROWS  (BATCH * SEQ)      // 4096
#define N_COLS  (3 * HIDDEN)       // 3072

// Scratch QKV, flat [u=2s+b][h][...]:
//   Q (u=0,1) and V (u=4,5): [t][d] row-major
//   K (u=2,3):               [d][t] row-major  (K^T, for mma B operand)
__device__ float g_qkv[(size_t)6 * N_HEADS * SEQ * HS];

// ---------------------------------------------------------------------------
// Helpers
// ---------------------------------------------------------------------------
__device__ __forceinline__ uint32_t smem_u32(const void* p) {
    uint32_t a;
    asm("{ .reg .u64 t; cvta.to.shared.u64 t, %1; cvt.u32.u64 %0, t; }"
        : "=r"(a) : "l"(p));
    return a;
}
__device__ __forceinline__ uint32_t f2tf(float f) {
    uint32_t u;
    asm("cvt.rna.tf32.f32 %0, %1;" : "=r"(u) : "f"(f));
    return u;
}
__device__ __forceinline__ void split_tf32(float v, uint32_t& hi, uint32_t& lo) {
    hi = f2tf(v);
    lo = f2tf(v - __uint_as_float(hi));
}
__device__ __forceinline__ void mma_tf32(float* d, const uint32_t* a,
                                         const uint32_t* b, const float* c) {
    asm volatile(
        "mma.sync.aligned.m16n8k8.row.col.f32.tf32.tf32.f32 "
        "{%0,%1,%2,%3}, {%4,%5,%6,%7}, {%8,%9}, {%10,%11,%12,%13};"
        : "=f"(d[0]), "=f"(d[1]), "=f"(d[2]), "=f"(d[3])
        : "r"(a[0]), "r"(a[1]), "r"(a[2]), "r"(a[3]),
          "r"(b[0]), "r"(b[1]),
          "f"(c[0]), "f"(c[1]), "f"(c[2]), "f"(c[3]));
}
__device__ __forceinline__ void cp16(uint32_t dst, const void* src) {
    asm volatile("cp.async.cg.shared.global [%0], [%1], 16;"
                 :: "r"(dst), "l"(src) : "memory");
}
#define CP_COMMIT() asm volatile("cp.async.commit_group;" ::: "memory")
#define CP_WAIT1()  asm volatile("cp.async.wait_group 1;" ::: "memory")
#define CP_WAIT0()  asm volatile("cp.async.wait_group 0;" ::: "memory")

// ---------------------------------------------------------------------------
// Kernel 1: QKV GEMM via mma.sync tf32, cp.async double-buffered raw tiles,
// tf32 conversion at fragment load.  Epilogue: bias + reshape scatter
// (g = 3r + c/1024; e = c%1024; u=g>>11; t=g&2047; h=e&15; d=e>>4),
// K third written d-major.
// ---------------------------------------------------------------------------
#define GBK   32
#define GNIT  (HIDDEN / GBK)          // 32
#define CSTR  132
#define GEMM_SMEM_BYTES (CSTR * 128 * 4)   // 67584; tile bufs use first 64KB

__global__ void __launch_bounds__(256, 2) qkv_gemm_tc(
    const float* __restrict__ x, const float* __restrict__ W,
    const float* __restrict__ bias)
{
    extern __shared__ float smf[];
    const uint32_t sbase = smem_u32(smf);
    const int tid  = threadIdx.x;
    const int lane = tid & 31;
    const int wid  = tid >> 5;
    const int wm   = wid & 1;
    const int wn   = wid >> 1;
    const int m0 = blockIdx.y * 128, n0 = blockIdx.x * 128;

    // Float offsets: A stages 0 / 4096, B stages 8192 / 12288
    const int a_row = tid >> 3;                 // 0..31 (+32i)
    const int a_k4  = (tid & 7) << 2;
    const int b_krw = tid >> 5;                 // 0..7 (+8i)
    const int b_n4  = (tid & 31) << 2;
    const float* Ag = x + (size_t)(m0 + a_row) * HIDDEN + a_k4;
    const float* Bg = W + (size_t)b_krw * N_COLS + n0 + b_n4;
    const uint32_t a_st = a_row * 32 + (a_k4 ^ (((uint32_t)(a_row & 7)) << 2));
    const uint32_t b_st = b_krw * 128 + (b_n4 ^ (((uint32_t)(b_krw & 3)) << 3));

    const int lr = lane >> 2, lc = lane & 3;

    float acc[4][4][4] = {};

    // Prologue: stage 0
    #pragma unroll
    for (int i = 0; i < 4; i++) {
        cp16(sbase + (a_st + i * 1024) * 4, Ag + (size_t)i * 32 * HIDDEN);
        cp16(sbase + (8192 + b_st + i * 1024) * 4, Bg + (size_t)i * 8 * N_COLS);
    }
    CP_COMMIT();

    for (int it = 0; it < GNIT; ++it) {
        const uint32_t buf = it & 1;
        if (it + 1 < GNIT) {
            const uint32_t nb = buf ^ 1;
            const float* Agn = Ag + (it + 1) * GBK;
            const float* Bgn = Bg + (size_t)(it + 1) * GBK * N_COLS;
            #pragma unroll
            for (int i = 0; i < 4; i++) {
                cp16(sbase + (nb * 4096 + a_st + i * 1024) * 4,
                     Agn + (size_t)i * 32 * HIDDEN);
                cp16(sbase + (8192 + nb * 4096 + b_st + i * 1024) * 4,
                     Bgn + (size_t)i * 8 * N_COLS);
            }
            CP_COMMIT();
            CP_WAIT1();
        } else {
            CP_WAIT0();
        }
        __syncthreads();

        const float* Ab = smf + buf * 4096;
        const float* Bb = smf + 8192 + buf * 4096;
        #pragma unroll
        for (int ks = 0; ks < 4; ks++) {
            const int k0 = ks * 8;
            uint32_t af[4][4], bf[4][2];
            #pragma unroll
            for (int mf = 0; mf < 4; mf++) {
                const int r = wm * 64 + mf * 16 + lr;
                const uint32_t i0 = (uint32_t)(k0 + lc) ^ (((uint32_t)(r & 7)) << 2);
                const uint32_t base = r * 32;
                af[mf][0] = f2tf(Ab[base + i0]);
                af[mf][1] = f2tf(Ab[base + 256 + i0]);
                af[mf][2] = f2tf(Ab[base + (i0 ^ 4)]);
                af[mf][3] = f2tf(Ab[base + 256 + (i0 ^ 4)]);
            }
            #pragma unroll
            for (int nf = 0; nf < 4; nf++) {
                const int n = wn * 32 + nf * 8 + lr;
                const int kk = k0 + lc;
                const uint32_t bi = kk * 128 + ((uint32_t)n ^ (((uint32_t)(kk & 3)) << 3));
                bf[nf][0] = f2tf(Bb[bi]);
                bf[nf][1] = f2tf(Bb[bi + 512]);
            }
            #pragma unroll
            for (int mf = 0; mf < 4; mf++)
                #pragma unroll
                for (int nf = 0; nf < 4; nf++)
                    mma_tf32(acc[mf][nf], af[mf], bf[nf], acc[mf][nf]);
        }
        __syncthreads();
    }

    // ---- Epilogue via smem ----
    float* Cs = smf;
    #pragma unroll
    for (int mf = 0; mf < 4; mf++) {
        const int r = wm * 64 + mf * 16 + lr;
        #pragma unroll
        for (int nf = 0; nf < 4; nf++) {
            const int c = wn * 32 + nf * 8 + 2 * lc;
            *(float2*)&Cs[r * CSTR + c]       = make_float2(acc[mf][nf][0], acc[mf][nf][1]);
            *(float2*)&Cs[(r + 8) * CSTR + c] = make_float2(acc[mf][nf][2], acc[mf][nf][3]);
        }
    }
    __syncthreads();

    {
        const int rr = tid >> 1;
        const int half = tid & 1;
        const int r = m0 + rr;
        const int g = 3 * r + (n0 >> 10);
        const int u = g >> 11, t = g & 2047;
        const int d0 = (n0 & 1023) >> 4;
        const bool isK = ((u >> 1) == 1);
        #pragma unroll
        for (int j = 0; j < 8; j++) {
            const int hh = half * 8 + j;
            float o[8];
            #pragma unroll
            for (int e = 0; e < 8; e++)
                o[e] = Cs[rr * CSTR + hh + 16 * e] + __ldg(&bias[n0 + hh + 16 * e]);
            float* base = g_qkv + (size_t)(u * 16 + hh) * (SEQ * HS);
            if (isK) {
                #pragma unroll
                for (int e = 0; e < 8; e++)
                    base[(size_t)(d0 + e) * SEQ + t] = o[e];
            } else {
                float* dst = base + (size_t)t * HS + d0;
                *(float4*)dst       = make_float4(o[0], o[1], o[2], o[3]);
                *(float4*)(dst + 4) = make_float4(o[4], o[5], o[6], o[7]);
            }
        }
    }
}

// ---------------------------------------------------------------------------
// Kernel 2: flash attention via mma.sync tf32, split-precision.
// BR=128 rows/CTA, 8 warps, BC=64. Raw fp32 tiles via cp.async:
// Q [128][64] single, K/V [2][64][64] double-buffered. Splits at frag load.
// smem = (8192 + 4*4096) floats = 96KB -> 2 CTAs/SM.
// ---------------------------------------------------------------------------
#define ATT_SMEM_BYTES (24576 * 4)

__global__ void __launch_bounds__(256, 2) attn_mma(float* __restrict__ out) {
    extern __shared__ float smf[];
    const uint32_t sbase = smem_u32(smf);
    float* Qs = smf;                       // [128][64] swizzled

    const int tid  = threadIdx.x;
    const int lane = tid & 31;
    const int w    = tid >> 5;             // warp 0..7, rows [16w,16w+16)
    const int lr   = lane >> 2, lc = lane & 3;
    const int qtile = (int)(gridDim.x - 1) - (int)blockIdx.x;  // long CTAs first
    const int h = blockIdx.y, b = blockIdx.z;
    const int q0 = qtile * 128;

    const float* qg  = g_qkv + (size_t)(b * 16 + h) * (SEQ * HS);        // [t][d]
    const float* ktg = g_qkv + (size_t)((2 + b) * 16 + h) * (SEQ * HS);  // [d][t]
    const float* vg  = g_qkv + (size_t)((4 + b) * 16 + h) * (SEQ * HS);  // [t][d]

    // ---- Prologue: async-load Q tile + K/V tile 0 ----
    #pragma unroll
    for (int i = 0; i < 8; i++) {
        int f = tid + i * 256;
        int r = f >> 4, d4 = (f & 15) << 2;
        uint32_t idx = r * 64 + ((uint32_t)d4 ^ (((uint32_t)(r & 7)) << 2));
        cp16(sbase + idx * 4, qg + (size_t)(q0 + r) * HS + d4);
    }
    #pragma unroll
    for (int i = 0; i < 4; i++) {
        int f = tid + i * 256;
        int rr = f >> 4, c4 = (f & 15) << 2;
        uint32_t kidx = rr * 64 + ((uint32_t)c4 ^ (((uint32_t)(rr & 3)) << 3));
        cp16(sbase + (8192 + kidx) * 4, ktg + (size_t)rr * SEQ + c4);
        cp16(sbase + (16384 + kidx) * 4, vg + (size_t)rr * HS + c4);
    }
    CP_COMMIT();

    float oacc[8][4];
    #pragma unroll
    for (int j = 0; j < 8; j++)
        #pragma unroll
        for (int k = 0; k < 4; k++) oacc[j][k] = 0.0f;
    float m0 = -1e30f, m1 = -1e30f, l0 = 0.0f, l1 = 0.0f;

    const int r16  = 16 * w + lr;
    const int nkt = 2 * qtile + 2;
    for (int kt = 0; kt < nkt; kt++) {
        const uint32_t buf = kt & 1;
        const int k0g = kt * 64;

        if (kt + 1 < nkt) {
            const uint32_t nb = buf ^ 1;
            const int k0n = (kt + 1) * 64;
            #pragma unroll
            for (int i = 0; i < 4; i++) {
                int f = tid + i * 256;
                int rr = f >> 4, c4 = (f & 15) << 2;
                uint32_t kidx = rr * 64 + ((uint32_t)c4 ^ (((uint32_t)(rr & 3)) << 3));
                cp16(sbase + (8192 + nb * 4096 + kidx) * 4,
                     ktg + (size_t)rr * SEQ + k0n + c4);
                cp16(sbase + (16384 + nb * 4096 + kidx) * 4,
                     vg + (size_t)(k0n + rr) * HS + c4);
            }
            CP_COMMIT();
            CP_WAIT1();
        } else {
            CP_WAIT0();
        }
        __syncthreads();

        if (k0g <= q0 + 16 * w + 15) {
            const float* Kb = smf + 8192 + buf * 4096;
            const float* Vb = smf + 16384 + buf * 4096;

            // ---- S = Q K^T (split 3-mma) ----
            float sacc[8][4];
            #pragma unroll
            for (int j = 0; j < 8; j++)
                #pragma unroll
                for (int k = 0; k < 4; k++) sacc[j][k] = 0.0f;

            #pragma unroll
            for (int ks = 0; ks < 8; ks++) {
                const int k8 = ks * 8;
                uint32_t ahi[4], alo[4];
                {
                    const uint32_t i0 = (uint32_t)(k8 + lc) ^ (((uint32_t)(r16 & 7)) << 2);
                    const uint32_t base = r16 * 64;
                    split_tf32(Qs[base + i0] * 0.125f,        ahi[0], alo[0]);
                    split_tf32(Qs[base + 512 + i0] * 0.125f,  ahi[1], alo[1]);
                    split_tf32(Qs[base + (i0 ^ 4)] * 0.125f,  ahi[2], alo[2]);
                    split_tf32(Qs[base + 512 + (i0 ^ 4)] * 0.125f, ahi[3], alo[3]);
                }
                const uint32_t kbase = (uint32_t)(k8 + lc) * 64;
                #pragma unroll
                for (int j = 0; j < 8; j++) {
                    const uint32_t bi = kbase + ((uint32_t)(8 * j + lr) ^ (((uint32_t)lc) << 3));
                    uint32_t bh[2], bl[2];
                    split_tf32(Kb[bi],       bh[0], bl[0]);
                    split_tf32(Kb[bi + 256], bh[1], bl[1]);
                    mma_tf32(sacc[j], ahi, bh, sacc[j]);
                    mma_tf32(sacc[j], alo, bh, sacc[j]);
                    mma_tf32(sacc[j], ahi, bl, sacc[j]);
                }
            }

            // ---- Causal mask (only near diagonal) ----
            const int row0 = q0 + 16 * w + lr;
            if (k0g + 63 > q0 + 16 * w) {
                #pragma unroll
                for (int j = 0; j < 8; j++) {
                    const int c0 = k0g + 8 * j + 2 * lc;
                    if (c0 > row0)         sacc[j][0] = -1e30f;
                    if (c0 + 1 > row0)     sacc[j][1] = -1e30f;
                    if (c0 > row0 + 8)     sacc[j][2] = -1e30f;
                    if (c0 + 1 > row0 + 8) sacc[j][3] = -1e30f;
                }
            }

            // ---- Online softmax (registers + quad shuffles) ----
            float ml0 = -1e30f, ml1 = -1e30f;
            #pragma unroll
            for (int j = 0; j < 8; j++) {
                ml0 = fmaxf(ml0, fmaxf(sacc[j][0], sacc[j][1]));
                ml1 = fmaxf(ml1, fmaxf(sacc[j][2], sacc[j][3]));
            }
            ml0 = fmaxf(ml0, __shfl_xor_sync(0xffffffffu, ml0, 1));
            ml0 = fmaxf(ml0, __shfl_xor_sync(0xffffffffu, ml0, 2));
            ml1 = fmaxf(ml1, __shfl_xor_sync(0xffffffffu, ml1, 1));
            ml1 = fmaxf(ml1, __shfl_xor_sync(0xffffffffu, ml1, 2));

            const float mn0 = fmaxf(m0, ml0), mn1 = fmaxf(m1, ml1);
            const float fac0 = __expf(m0 - mn0), fac1 = __expf(m1 - mn1);
            float ls0 = 0.0f, ls1 = 0.0f;
            #pragma unroll
            for (int j = 0; j < 8; j++) {
                float p0 = __expf(sacc[j][0] - mn0);
                float p1 = __expf(sacc[j][1] - mn0);
                float p2 = __expf(sacc[j][2] - mn1);
                float p3 = __expf(sacc[j][3] - mn1);
                sacc[j][0] = p0; sacc[j][1] = p1; sacc[j][2] = p2; sacc[j][3] = p3;
                ls0 += p0 + p1; ls1 += p2 + p3;
            }
            ls0 += __shfl_xor_sync(0xffffffffu, ls0, 1);
            ls0 += __shfl_xor_sync(0xffffffffu, ls0, 2);
            ls1 += __shfl_xor_sync(0xffffffffu, ls1, 1);
            ls1 += __shfl_xor_sync(0xffffffffu, ls1, 2);
            l0 = l0 * fac0 + ls0;
            l1 = l1 * fac1 + ls1;
            m0 = mn0; m1 = mn1;

            #pragma unroll
            for (int j = 0; j < 8; j++) {
                oacc[j][0] *= fac0; oacc[j][1] *= fac0;
                oacc[j][2] *= fac1; oacc[j][3] *= fac1;
            }

            // ---- O += P V : shuffle D-frag -> A-frag, split P, tf32 V ----
            const int srcA = (lr << 2) + (lc >> 1);
            const int srcB = srcA + 2;
            const int sel  = lc & 1;
            #pragma unroll
            for (int ks = 0; ks < 8; ks++) {
                float x0 = __shfl_sync(0xffffffffu, sacc[ks][0], srcA);
                float x1 = __shfl_sync(0xffffffffu, sacc[ks][1], srcA);
                float y0 = __shfl_sync(0xffffffffu, sacc[ks][2], srcA);
                float y1 = __shfl_sync(0xffffffffu, sacc[ks][3], srcA);
                float z0 = __shfl_sync(0xffffffffu, sacc[ks][0], srcB);
                float z1 = __shfl_sync(0xffffffffu, sacc[ks][1], srcB);
                float w0 = __shfl_sync(0xffffffffu, sacc[ks][2], srcB);
                float w1 = __shfl_sync(0xffffffffu, sacc[ks][3], srcB);
                float pa0 = sel ? x1 : x0;
                float pa1 = sel ? y1 : y0;
                float pa2 = sel ? z1 : z0;
                float pa3 = sel ? w1 : w0;
                uint32_t phi[4], plo[4];
                split_tf32(pa0, phi[0], plo[0]);
                split_tf32(pa1, phi[1], plo[1]);
                split_tf32(pa2, phi[2], plo[2]);
                split_tf32(pa3, phi[3], plo[3]);

                const uint32_t vbase = (uint32_t)(ks * 8 + lc) * 64;
                #pragma unroll
                for (int j = 0; j < 8; j++) {
                    const uint32_t bi = vbase + ((uint32_t)(8 * j + lr) ^ (((uint32_t)lc) << 3));
                    uint32_t vb[2];
                    vb[0] = f2tf(Vb[bi]);
                    vb[1] = f2tf(Vb[bi + 256]);
                    mma_tf32(oacc[j], phi, vb, oacc[j]);
                    mma_tf32(oacc[j], plo, vb, oacc[j]);
                }
            }
        }
        __syncthreads();
    }

    // ---- Write O, normalized ----
    const float inv0 = 1.0f / l0, inv1 = 1.0f / l1;
    const int row = q0 + 16 * w + lr;
    float* ob0 = out + ((size_t)(b * SEQ + row)) * HIDDEN + h * HS;
    float* ob1 = out + ((size_t)(b * SEQ + row + 8)) * HIDDEN + h * HS;
    #pragma unroll
    for (int j = 0; j < 8; j++) {
        const int c = 8 * j + 2 * lc;
        *(float2*)(ob0 + c) = make_float2(oacc[j][0] * inv0, oacc[j][1] * inv0);
        *(float2*)(ob1 + c) = make_float2(oacc[j][2] * inv1, oacc[j][3] * inv1);
    }
}

// ---------------------------------------------------------------------------
// Launch
// ---------------------------------------------------------------------------
extern "C" void kernel_launch(void* const* d_in, const int* in_sizes, int n_in,
                              void* d_out, int out_size) {
    const float* x    = (const float*)d_in[0];
    const float* W    = (const float*)d_in[1];
    const float* bias = (const float*)d_in[2];
    float* out = (float*)d_out;

    cudaFuncSetAttribute(qkv_gemm_tc,
                         cudaFuncAttributeMaxDynamicSharedMemorySize,
                         GEMM_SMEM_BYTES);
    qkv_gemm_tc<<<dim3(N_COLS / 128, M_ROWS / 128), 256, GEMM_SMEM_BYTES>>>(
        x, W, bias);

    cudaFuncSetAttribute(attn_mma,
                         cudaFuncAttributeMaxDynamicSharedMemorySize,
                         ATT_SMEM_BYTES);
    attn_mma<<<dim3(SEQ / 128, N_HEADS, BATCH), 256, ATT_SMEM_BYTES>>>(out);
}

// round 7
// speedup vs baseline: 1.1781x; 1.1781x over previous
#include <cuda_runtime.h>
#include <cstdint>
#include <math.h>

#define N_HEADS 16
#define HIDDEN  1024
#define HS      64
#define BATCH   2
#define SEQ     2048
#define M_ROWS  (BATCH * SEQ)      // 4096
#define N_COLS  (3 * HIDDEN)       // 3072

// Scratch QKV, flat [u=2s+b][h][...]:
//   Q (u=0,1) and V (u=4,5): [t][d] row-major
//   K (u=2,3):               [d][t] row-major  (K^T, for mma B operand)
__device__ float g_qkv[(size_t)6 * N_HEADS * SEQ * HS];

// ---------------------------------------------------------------------------
// Helpers
// ---------------------------------------------------------------------------
__device__ __forceinline__ uint32_t smem_u32(const void* p) {
    uint32_t a;
    asm("{ .reg .u64 t; cvta.to.shared.u64 t, %1; cvt.u32.u64 %0, t; }"
        : "=r"(a) : "l"(p));
    return a;
}
__device__ __forceinline__ uint32_t f2tf(float f) {
    uint32_t u;
    asm("cvt.rna.tf32.f32 %0, %1;" : "=r"(u) : "f"(f));
    return u;
}
__device__ __forceinline__ void split_tf32(float v, uint32_t& hi, uint32_t& lo) {
    hi = f2tf(v);
    lo = f2tf(v - __uint_as_float(hi));
}
__device__ __forceinline__ void mma_tf32(float* d, const uint32_t* a,
                                         const uint32_t* b, const float* c) {
    asm volatile(
        "mma.sync.aligned.m16n8k8.row.col.f32.tf32.tf32.f32 "
        "{%0,%1,%2,%3}, {%4,%5,%6,%7}, {%8,%9}, {%10,%11,%12,%13};"
        : "=f"(d[0]), "=f"(d[1]), "=f"(d[2]), "=f"(d[3])
        : "r"(a[0]), "r"(a[1]), "r"(a[2]), "r"(a[3]),
          "r"(b[0]), "r"(b[1]),
          "f"(c[0]), "f"(c[1]), "f"(c[2]), "f"(c[3]));
}
__device__ __forceinline__ void cp16(uint32_t dst, const void* src) {
    asm volatile("cp.async.cg.shared.global [%0], [%1], 16;"
                 :: "r"(dst), "l"(src) : "memory");
}
#define CP_COMMIT() asm volatile("cp.async.commit_group;" ::: "memory")
#define CP_WAIT1()  asm volatile("cp.async.wait_group 1;" ::: "memory")
#define CP_WAIT0()  asm volatile("cp.async.wait_group 0;" ::: "memory")

// ---------------------------------------------------------------------------
// Kernel 1: QKV GEMM via mma.sync tf32 (R6 version, measured ~210us).
// cp.async double-buffered raw tiles, tf32 cvt at fragment load.
// Epilogue: bias + reshape scatter (g = 3r + c/1024; e = c%1024;
// u=g>>11; t=g&2047; h=e&15; d=e>>4); K third written d-major.
// ---------------------------------------------------------------------------
#define GBK   32
#define GNIT  (HIDDEN / GBK)          // 32
#define CSTR  132
#define GEMM_SMEM_BYTES (CSTR * 128 * 4)

__global__ void __launch_bounds__(256, 2) qkv_gemm_tc(
    const float* __restrict__ x, const float* __restrict__ W,
    const float* __restrict__ bias)
{
    extern __shared__ float smf[];
    const uint32_t sbase = smem_u32(smf);
    const int tid  = threadIdx.x;
    const int lane = tid & 31;
    const int wid  = tid >> 5;
    const int wm   = wid & 1;
    const int wn   = wid >> 1;
    const int m0 = blockIdx.y * 128, n0 = blockIdx.x * 128;

    const int a_row = tid >> 3;
    const int a_k4  = (tid & 7) << 2;
    const int b_krw = tid >> 5;
    const int b_n4  = (tid & 31) << 2;
    const float* Ag = x + (size_t)(m0 + a_row) * HIDDEN + a_k4;
    const float* Bg = W + (size_t)b_krw * N_COLS + n0 + b_n4;
    const uint32_t a_st = a_row * 32 + (a_k4 ^ (((uint32_t)(a_row & 7)) << 2));
    const uint32_t b_st = b_krw * 128 + (b_n4 ^ (((uint32_t)(b_krw & 3)) << 3));

    const int lr = lane >> 2, lc = lane & 3;

    float acc[4][4][4] = {};

    #pragma unroll
    for (int i = 0; i < 4; i++) {
        cp16(sbase + (a_st + i * 1024) * 4, Ag + (size_t)i * 32 * HIDDEN);
        cp16(sbase + (8192 + b_st + i * 1024) * 4, Bg + (size_t)i * 8 * N_COLS);
    }
    CP_COMMIT();

    for (int it = 0; it < GNIT; ++it) {
        const uint32_t buf = it & 1;
        if (it + 1 < GNIT) {
            const uint32_t nb = buf ^ 1;
            const float* Agn = Ag + (it + 1) * GBK;
            const float* Bgn = Bg + (size_t)(it + 1) * GBK * N_COLS;
            #pragma unroll
            for (int i = 0; i < 4; i++) {
                cp16(sbase + (nb * 4096 + a_st + i * 1024) * 4,
                     Agn + (size_t)i * 32 * HIDDEN);
                cp16(sbase + (8192 + nb * 4096 + b_st + i * 1024) * 4,
                     Bgn + (size_t)i * 8 * N_COLS);
            }
            CP_COMMIT();
            CP_WAIT1();
        } else {
            CP_WAIT0();
        }
        __syncthreads();

        const float* Ab = smf + buf * 4096;
        const float* Bb = smf + 8192 + buf * 4096;
        #pragma unroll
        for (int ks = 0; ks < 4; ks++) {
            const int k0 = ks * 8;
            uint32_t af[4][4], bf[4][2];
            #pragma unroll
            for (int mf = 0; mf < 4; mf++) {
                const int r = wm * 64 + mf * 16 + lr;
                const uint32_t i0 = (uint32_t)(k0 + lc) ^ (((uint32_t)(r & 7)) << 2);
                const uint32_t base = r * 32;
                af[mf][0] = f2tf(Ab[base + i0]);
                af[mf][1] = f2tf(Ab[base + 256 + i0]);
                af[mf][2] = f2tf(Ab[base + (i0 ^ 4)]);
                af[mf][3] = f2tf(Ab[base + 256 + (i0 ^ 4)]);
            }
            #pragma unroll
            for (int nf = 0; nf < 4; nf++) {
                const int n = wn * 32 + nf * 8 + lr;
                const int kk = k0 + lc;
                const uint32_t bi = kk * 128 + ((uint32_t)n ^ (((uint32_t)(kk & 3)) << 3));
                bf[nf][0] = f2tf(Bb[bi]);
                bf[nf][1] = f2tf(Bb[bi + 512]);
            }
            #pragma unroll
            for (int mf = 0; mf < 4; mf++)
                #pragma unroll
                for (int nf = 0; nf < 4; nf++)
                    mma_tf32(acc[mf][nf], af[mf], bf[nf], acc[mf][nf]);
        }
        __syncthreads();
    }

    // ---- Epilogue via smem ----
    float* Cs = smf;
    #pragma unroll
    for (int mf = 0; mf < 4; mf++) {
        const int r = wm * 64 + mf * 16 + lr;
        #pragma unroll
        for (int nf = 0; nf < 4; nf++) {
            const int c = wn * 32 + nf * 8 + 2 * lc;
            *(float2*)&Cs[r * CSTR + c]       = make_float2(acc[mf][nf][0], acc[mf][nf][1]);
            *(float2*)&Cs[(r + 8) * CSTR + c] = make_float2(acc[mf][nf][2], acc[mf][nf][3]);
        }
    }
    __syncthreads();

    {
        const int rr = tid >> 1;
        const int half = tid & 1;
        const int r = m0 + rr;
        const int g = 3 * r + (n0 >> 10);
        const int u = g >> 11, t = g & 2047;
        const int d0 = (n0 & 1023) >> 4;
        const bool isK = ((u >> 1) == 1);
        #pragma unroll
        for (int j = 0; j < 8; j++) {
            const int hh = half * 8 + j;
            float o[8];
            #pragma unroll
            for (int e = 0; e < 8; e++)
                o[e] = Cs[rr * CSTR + hh + 16 * e] + __ldg(&bias[n0 + hh + 16 * e]);
            float* base = g_qkv + (size_t)(u * 16 + hh) * (SEQ * HS);
            if (isK) {
                #pragma unroll
                for (int e = 0; e < 8; e++)
                    base[(size_t)(d0 + e) * SEQ + t] = o[e];
            } else {
                float* dst = base + (size_t)t * HS + d0;
                *(float4*)dst       = make_float4(o[0], o[1], o[2], o[3]);
                *(float4*)(dst + 4) = make_float4(o[4], o[5], o[6], o[7]);
            }
        }
    }
}

// ---------------------------------------------------------------------------
// Kernel 2: flash attention via mma.sync tf32, split-precision.
// R5 numerics (split ONCE into smem: Qhi/Qlo [128][64], Khi/Klo [64][64],
// V tf32 [64][64]); staging registers cut to 16 (K quad then V quad) and
// __launch_bounds__(256,2) for 2 CTAs/SM (smem 112KB*2 = 224KB <= 228KB).
// ---------------------------------------------------------------------------
#define ATT_SMEM_U32 28672   // 8192*2 + 4096*3
#define ATT_SMEM_BYTES (ATT_SMEM_U32 * 4)

__global__ void __launch_bounds__(256, 2) attn_mma(float* __restrict__ out) {
    extern __shared__ uint32_t sm[];
    uint32_t* Qhi = sm;                 // 8192
    uint32_t* Qlo = sm + 8192;          // 8192
    uint32_t* Khi = sm + 16384;         // 4096
    uint32_t* Klo = sm + 20480;         // 4096
    uint32_t* Vs  = sm + 24576;         // 4096

    const int tid  = threadIdx.x;
    const int lane = tid & 31;
    const int w    = tid >> 5;          // warp 0..7, rows [16w,16w+16)
    const int lr   = lane >> 2, lc = lane & 3;
    const int qtile = (int)(gridDim.x - 1) - (int)blockIdx.x;  // long CTAs first
    const int h = blockIdx.y, b = blockIdx.z;
    const int q0 = qtile * 128;

    const float* qg  = g_qkv + (size_t)(b * 16 + h) * (SEQ * HS);        // [t][d]
    const float* ktg = g_qkv + (size_t)((2 + b) * 16 + h) * (SEQ * HS);  // [d][t]
    const float* vg  = g_qkv + (size_t)((4 + b) * 16 + h) * (SEQ * HS);  // [t][d]

    // ---- Load Q tile (scaled by 2^-3, exact), split hi/lo once ----
    #pragma unroll
    for (int i = 0; i < 8; i++) {
        int f = tid + i * 256;
        int r = f >> 4, d4 = (f & 15) << 2;
        float4 v = *(const float4*)(qg + (size_t)(q0 + r) * HS + d4);
        v.x *= 0.125f; v.y *= 0.125f; v.z *= 0.125f; v.w *= 0.125f;
        uint32_t idx = r * 64 + ((uint32_t)d4 ^ (((uint32_t)(r & 7)) << 2));
        uint4 hi, lo;
        split_tf32(v.x, hi.x, lo.x); split_tf32(v.y, hi.y, lo.y);
        split_tf32(v.z, hi.z, lo.z); split_tf32(v.w, hi.w, lo.w);
        *(uint4*)&Qhi[idx] = hi;
        *(uint4*)&Qlo[idx] = lo;
    }

    float oacc[8][4];
    #pragma unroll
    for (int j = 0; j < 8; j++)
        #pragma unroll
        for (int k = 0; k < 4; k++) oacc[j][k] = 0.0f;
    float m0 = -1e30f, m1 = -1e30f, l0 = 0.0f, l1 = 0.0f;

    // Per-thread K/V staging addresses (quad per thread per phase)
    const int st_r  = tid >> 4;               // 0..15 (+16i)
    const int st_c4 = (tid & 15) << 2;

    const int nkt = 2 * qtile + 2;
    for (int kt = 0; kt < nkt; kt++) {
        const int k0g = kt * 64;

        // ---- K^T quad: LDG (issued pre-sync for overlap) ----
        float4 kreg[4];
        uint32_t kidx[4];
        #pragma unroll
        for (int i = 0; i < 4; i++) {
            int rr = st_r + i * 16;
            kreg[i] = *(const float4*)(ktg + (size_t)rr * SEQ + k0g + st_c4);
            kidx[i] = rr * 64 + ((uint32_t)st_c4 ^ (((uint32_t)(rr & 3)) << 3));
        }
        __syncthreads();   // prev-tile consumers done
        #pragma unroll
        for (int i = 0; i < 4; i++) {
            uint4 hi, lo;
            split_tf32(kreg[i].x, hi.x, lo.x); split_tf32(kreg[i].y, hi.y, lo.y);
            split_tf32(kreg[i].z, hi.z, lo.z); split_tf32(kreg[i].w, hi.w, lo.w);
            *(uint4*)&Khi[kidx[i]] = hi;
            *(uint4*)&Klo[kidx[i]] = lo;
        }
        // ---- V quad: LDG then cvt+store (reuses staging regs) ----
        float4 vreg[4];
        #pragma unroll
        for (int i = 0; i < 4; i++)
            vreg[i] = *(const float4*)(vg + (size_t)(k0g + st_r + i * 16) * HS + st_c4);
        #pragma unroll
        for (int i = 0; i < 4; i++) {
            uint4 vv;
            vv.x = f2tf(vreg[i].x); vv.y = f2tf(vreg[i].y);
            vv.z = f2tf(vreg[i].z); vv.w = f2tf(vreg[i].w);
            *(uint4*)&Vs[kidx[i]] = vv;
        }
        __syncthreads();   // tiles visible

        // Full-skip: all cols of this tile above all rows of this warp
        if (k0g > q0 + 16 * w + 15) continue;

        // ---- S = Q K^T (split 3-mma) ----
        float sacc[8][4];
        #pragma unroll
        for (int j = 0; j < 8; j++)
            #pragma unroll
            for (int k = 0; k < 4; k++) sacc[j][k] = 0.0f;

        #pragma unroll
        for (int ks = 0; ks < 8; ks++) {
            const int k8 = ks * 8;
            uint32_t ahi[4], alo[4];
            {
                const int r = 16 * w + lr;
                const uint32_t i0 = (uint32_t)(k8 + lc) ^ (((uint32_t)(r & 7)) << 2);
                const uint32_t base = r * 64;
                ahi[0] = Qhi[base + i0];       alo[0] = Qlo[base + i0];
                ahi[1] = Qhi[base + 512 + i0]; alo[1] = Qlo[base + 512 + i0];
                ahi[2] = Qhi[base + (i0 ^ 4)]; alo[2] = Qlo[base + (i0 ^ 4)];
                ahi[3] = Qhi[base + 512 + (i0 ^ 4)]; alo[3] = Qlo[base + 512 + (i0 ^ 4)];
            }
            const uint32_t kbase = (uint32_t)(k8 + lc) * 64;
            #pragma unroll
            for (int j = 0; j < 8; j++) {
                const uint32_t bi = kbase + ((uint32_t)(8 * j + lr) ^ (((uint32_t)lc) << 3));
                uint32_t bh[2] = { Khi[bi], Khi[bi + 256] };
                mma_tf32(sacc[j], ahi, bh, sacc[j]);
                mma_tf32(sacc[j], alo, bh, sacc[j]);
                uint32_t bl[2] = { Klo[bi], Klo[bi + 256] };
                mma_tf32(sacc[j], ahi, bl, sacc[j]);
            }
        }

        // ---- Causal mask (only near diagonal) ----
        const int row0 = q0 + 16 * w + lr;
        if (k0g + 63 > q0 + 16 * w) {
            #pragma unroll
            for (int j = 0; j < 8; j++) {
                const int c0 = k0g + 8 * j + 2 * lc;
                if (c0 > row0)         sacc[j][0] = -1e30f;
                if (c0 + 1 > row0)     sacc[j][1] = -1e30f;
                if (c0 > row0 + 8)     sacc[j][2] = -1e30f;
                if (c0 + 1 > row0 + 8) sacc[j][3] = -1e30f;
            }
        }

        // ---- Online softmax (registers + quad shuffles) ----
        float ml0 = -1e30f, ml1 = -1e30f;
        #pragma unroll
        for (int j = 0; j < 8; j++) {
            ml0 = fmaxf(ml0, fmaxf(sacc[j][0], sacc[j][1]));
            ml1 = fmaxf(ml1, fmaxf(sacc[j][2], sacc[j][3]));
        }
        ml0 = fmaxf(ml0, __shfl_xor_sync(0xffffffffu, ml0, 1));
        ml0 = fmaxf(ml0, __shfl_xor_sync(0xffffffffu, ml0, 2));
        ml1 = fmaxf(ml1, __shfl_xor_sync(0xffffffffu, ml1, 1));
        ml1 = fmaxf(ml1, __shfl_xor_sync(0xffffffffu, ml1, 2));

        const float mn0 = fmaxf(m0, ml0), mn1 = fmaxf(m1, ml1);
        const float fac0 = __expf(m0 - mn0), fac1 = __expf(m1 - mn1);
        float ls0 = 0.0f, ls1 = 0.0f;
        #pragma unroll
        for (int j = 0; j < 8; j++) {
            float p0 = __expf(sacc[j][0] - mn0);
            float p1 = __expf(sacc[j][1] - mn0);
            float p2 = __expf(sacc[j][2] - mn1);
            float p3 = __expf(sacc[j][3] - mn1);
            sacc[j][0] = p0; sacc[j][1] = p1; sacc[j][2] = p2; sacc[j][3] = p3;
            ls0 += p0 + p1; ls1 += p2 + p3;
        }
        ls0 += __shfl_xor_sync(0xffffffffu, ls0, 1);
        ls0 += __shfl_xor_sync(0xffffffffu, ls0, 2);
        ls1 += __shfl_xor_sync(0xffffffffu, ls1, 1);
        ls1 += __shfl_xor_sync(0xffffffffu, ls1, 2);
        l0 = l0 * fac0 + ls0;
        l1 = l1 * fac1 + ls1;
        m0 = mn0; m1 = mn1;

        #pragma unroll
        for (int j = 0; j < 8; j++) {
            oacc[j][0] *= fac0; oacc[j][1] *= fac0;
            oacc[j][2] *= fac1; oacc[j][3] *= fac1;
        }

        // ---- O += P V : shuffle D-frag -> A-frag, split P, tf32 V ----
        const int srcA = (lr << 2) + (lc >> 1);
        const int srcB = srcA + 2;
        const int sel  = lc & 1;
        #pragma unroll
        for (int ks = 0; ks < 8; ks++) {
            float x0 = __shfl_sync(0xffffffffu, sacc[ks][0], srcA);
            float x1 = __shfl_sync(0xffffffffu, sacc[ks][1], srcA);
            float y0 = __shfl_sync(0xffffffffu, sacc[ks][2], srcA);
            float y1 = __shfl_sync(0xffffffffu, sacc[ks][3], srcA);
            float z0 = __shfl_sync(0xffffffffu, sacc[ks][0], srcB);
            float z1 = __shfl_sync(0xffffffffu, sacc[ks][1], srcB);
            float w0 = __shfl_sync(0xffffffffu, sacc[ks][2], srcB);
            float w1 = __shfl_sync(0xffffffffu, sacc[ks][3], srcB);
            float pa0 = sel ? x1 : x0;
            float pa1 = sel ? y1 : y0;
            float pa2 = sel ? z1 : z0;
            float pa3 = sel ? w1 : w0;
            uint32_t phi[4], plo[4];
            split_tf32(pa0, phi[0], plo[0]);
            split_tf32(pa1, phi[1], plo[1]);
            split_tf32(pa2, phi[2], plo[2]);
            split_tf32(pa3, phi[3], plo[3]);

            const uint32_t vbase = (uint32_t)(ks * 8 + lc) * 64;
            #pragma unroll
            for (int j = 0; j < 8; j++) {
                const uint32_t bi = vbase + ((uint32_t)(8 * j + lr) ^ (((uint32_t)lc) << 3));
                uint32_t vb[2] = { Vs[bi], Vs[bi + 256] };
                mma_tf32(oacc[j], phi, vb, oacc[j]);
                mma_tf32(oacc[j], plo, vb, oacc[j]);
            }
        }
    }

    // ---- Write O, normalized ----
    const float inv0 = 1.0f / l0, inv1 = 1.0f / l1;
    const int row = q0 + 16 * w + lr;
    float* ob0 = out + ((size_t)(b * SEQ + row)) * HIDDEN + h * HS;
    float* ob1 = out + ((size_t)(b * SEQ + row + 8)) * HIDDEN + h * HS;
    #pragma unroll
    for (int j = 0; j < 8; j++) {
        const int c = 8 * j + 2 * lc;
        *(float2*)(ob0 + c) = make_float2(oacc[j][0] * inv0, oacc[j][1] * inv0);
        *(float2*)(ob1 + c) = make_float2(oacc[j][2] * inv1, oacc[j][3] * inv1);
    }
}

// ---------------------------------------------------------------------------
// Launch
// ---------------------------------------------------------------------------
extern "C" void kernel_launch(void* const* d_in, const int* in_sizes, int n_in,
                              void* d_out, int out_size) {
    const float* x    = (const float*)d_in[0];
    const float* W    = (const float*)d_in[1];
    const float* bias = (const float*)d_in[2];
    float* out = (float*)d_out;

    cudaFuncSetAttribute(qkv_gemm_tc,
                         cudaFuncAttributeMaxDynamicSharedMemorySize,
                         GEMM_SMEM_BYTES);
    qkv_gemm_tc<<<dim3(N_COLS / 128, M_ROWS / 128), 256, GEMM_SMEM_BYTES>>>(
        x, W, bias);

    cudaFuncSetAttribute(attn_mma,
                         cudaFuncAttributeMaxDynamicSharedMemorySize,
                         ATT_SMEM_BYTES);
    attn_mma<<<dim3(SEQ / 128, N_HEADS, BATCH), 256, ATT_SMEM_BYTES>>>(out);
}

// round 8
// speedup vs baseline: 1.5085x; 1.2805x over previous
#include <cuda_runtime.h>
#include <cuda_bf16.h>
#include <cstdint>
#include <math.h>

#define N_HEADS 16
#define HIDDEN  1024
#define HS      64
#define BATCH   2
#define SEQ     2048
#define M_ROWS  (BATCH * SEQ)      // 4096
#define N_COLS  (3 * HIDDEN)       // 3072

// Scratch QKV, flat [u=2s+b][h][...]:
//   Q (u=0,1) and K (u=2,3): [t][d] row-major
//   V (u=4,5):               [d][t] row-major  (V^T, for bf16 mma B operand)
__device__ float g_qkv[(size_t)6 * N_HEADS * SEQ * HS];

// ---------------------------------------------------------------------------
// Helpers
// ---------------------------------------------------------------------------
__device__ __forceinline__ uint32_t smem_u32(const void* p) {
    uint32_t a;
    asm("{ .reg .u64 t; cvta.to.shared.u64 t, %1; cvt.u32.u64 %0, t; }"
        : "=r"(a) : "l"(p));
    return a;
}
__device__ __forceinline__ uint32_t f2tf(float f) {
    uint32_t u;
    asm("cvt.rna.tf32.f32 %0, %1;" : "=r"(u) : "f"(f));
    return u;
}
__device__ __forceinline__ void mma_tf32(float* d, const uint32_t* a,
                                         const uint32_t* b, const float* c) {
    asm volatile(
        "mma.sync.aligned.m16n8k8.row.col.f32.tf32.tf32.f32 "
        "{%0,%1,%2,%3}, {%4,%5,%6,%7}, {%8,%9}, {%10,%11,%12,%13};"
        : "=f"(d[0]), "=f"(d[1]), "=f"(d[2]), "=f"(d[3])
        : "r"(a[0]), "r"(a[1]), "r"(a[2]), "r"(a[3]),
          "r"(b[0]), "r"(b[1]),
          "f"(c[0]), "f"(c[1]), "f"(c[2]), "f"(c[3]));
}
__device__ __forceinline__ void mma_bf16(float* d, const uint32_t* a,
                                         const uint32_t* b) {
    asm volatile(
        "mma.sync.aligned.m16n8k16.row.col.f32.bf16.bf16.f32 "
        "{%0,%1,%2,%3}, {%4,%5,%6,%7}, {%8,%9}, {%0,%1,%2,%3};"
        : "+f"(d[0]), "+f"(d[1]), "+f"(d[2]), "+f"(d[3])
        : "r"(a[0]), "r"(a[1]), "r"(a[2]), "r"(a[3]),
          "r"(b[0]), "r"(b[1]));
}
// Split (x,y) into bf16x2 hi and bf16x2 lo (residual). Low half = x (= lower k).
__device__ __forceinline__ void split_bf2(float x, float y,
                                          uint32_t& hi, uint32_t& lo) {
    __nv_bfloat16 hx = __float2bfloat16_rn(x);
    __nv_bfloat16 hy = __float2bfloat16_rn(y);
    __nv_bfloat162 hp; hp.x = hx; hp.y = hy;
    hi = *reinterpret_cast<uint32_t*>(&hp);
    __nv_bfloat162 lp;
    lp.x = __float2bfloat16_rn(x - __bfloat162float(hx));
    lp.y = __float2bfloat16_rn(y - __bfloat162float(hy));
    lo = *reinterpret_cast<uint32_t*>(&lp);
}
__device__ __forceinline__ void cp16(uint32_t dst, const void* src) {
    asm volatile("cp.async.cg.shared.global [%0], [%1], 16;"
                 :: "r"(dst), "l"(src) : "memory");
}
#define CP_COMMIT() asm volatile("cp.async.commit_group;" ::: "memory")
#define CP_WAIT1()  asm volatile("cp.async.wait_group 1;" ::: "memory")
#define CP_WAIT0()  asm volatile("cp.async.wait_group 0;" ::: "memory")

// ---------------------------------------------------------------------------
// Kernel 1: QKV GEMM via mma.sync tf32 (unchanged from R7 except: the V third
// is written transposed [d][t]; K is now natural [t][d]).
// Reshape algebra: g = 3r + c/1024; e = c%1024; u=g>>11; t=g&2047;
// h=e&15; d=e>>4.
// ---------------------------------------------------------------------------
#define GBK   32
#define GNIT  (HIDDEN / GBK)          // 32
#define CSTR  132
#define GEMM_SMEM_BYTES (CSTR * 128 * 4)

__global__ void __launch_bounds__(256, 2) qkv_gemm_tc(
    const float* __restrict__ x, const float* __restrict__ W,
    const float* __restrict__ bias)
{
    extern __shared__ float smf[];
    const uint32_t sbase = smem_u32(smf);
    const int tid  = threadIdx.x;
    const int lane = tid & 31;
    const int wid  = tid >> 5;
    const int wm   = wid & 1;
    const int wn   = wid >> 1;
    const int m0 = blockIdx.y * 128, n0 = blockIdx.x * 128;

    const int a_row = tid >> 3;
    const int a_k4  = (tid & 7) << 2;
    const int b_krw = tid >> 5;
    const int b_n4  = (tid & 31) << 2;
    const float* Ag = x + (size_t)(m0 + a_row) * HIDDEN + a_k4;
    const float* Bg = W + (size_t)b_krw * N_COLS + n0 + b_n4;
    const uint32_t a_st = a_row * 32 + (a_k4 ^ (((uint32_t)(a_row & 7)) << 2));
    const uint32_t b_st = b_krw * 128 + (b_n4 ^ (((uint32_t)(b_krw & 3)) << 3));

    const int lr = lane >> 2, lc = lane & 3;

    float acc[4][4][4] = {};

    #pragma unroll
    for (int i = 0; i < 4; i++) {
        cp16(sbase + (a_st + i * 1024) * 4, Ag + (size_t)i * 32 * HIDDEN);
        cp16(sbase + (8192 + b_st + i * 1024) * 4, Bg + (size_t)i * 8 * N_COLS);
    }
    CP_COMMIT();

    for (int it = 0; it < GNIT; ++it) {
        const uint32_t buf = it & 1;
        if (it + 1 < GNIT) {
            const uint32_t nb = buf ^ 1;
            const float* Agn = Ag + (it + 1) * GBK;
            const float* Bgn = Bg + (size_t)(it + 1) * GBK * N_COLS;
            #pragma unroll
            for (int i = 0; i < 4; i++) {
                cp16(sbase + (nb * 4096 + a_st + i * 1024) * 4,
                     Agn + (size_t)i * 32 * HIDDEN);
                cp16(sbase + (8192 + nb * 4096 + b_st + i * 1024) * 4,
                     Bgn + (size_t)i * 8 * N_COLS);
            }
            CP_COMMIT();
            CP_WAIT1();
        } else {
            CP_WAIT0();
        }
        __syncthreads();

        const float* Ab = smf + buf * 4096;
        const float* Bb = smf + 8192 + buf * 4096;
        #pragma unroll
        for (int ks = 0; ks < 4; ks++) {
            const int k0 = ks * 8;
            uint32_t af[4][4], bf[4][2];
            #pragma unroll
            for (int mf = 0; mf < 4; mf++) {
                const int r = wm * 64 + mf * 16 + lr;
                const uint32_t i0 = (uint32_t)(k0 + lc) ^ (((uint32_t)(r & 7)) << 2);
                const uint32_t base = r * 32;
                af[mf][0] = f2tf(Ab[base + i0]);
                af[mf][1] = f2tf(Ab[base + 256 + i0]);
                af[mf][2] = f2tf(Ab[base + (i0 ^ 4)]);
                af[mf][3] = f2tf(Ab[base + 256 + (i0 ^ 4)]);
            }
            #pragma unroll
            for (int nf = 0; nf < 4; nf++) {
                const int n = wn * 32 + nf * 8 + lr;
                const int kk = k0 + lc;
                const uint32_t bi = kk * 128 + ((uint32_t)n ^ (((uint32_t)(kk & 3)) << 3));
                bf[nf][0] = f2tf(Bb[bi]);
                bf[nf][1] = f2tf(Bb[bi + 512]);
            }
            #pragma unroll
            for (int mf = 0; mf < 4; mf++)
                #pragma unroll
                for (int nf = 0; nf < 4; nf++)
                    mma_tf32(acc[mf][nf], af[mf], bf[nf], acc[mf][nf]);
        }
        __syncthreads();
    }

    // ---- Epilogue via smem ----
    float* Cs = smf;
    #pragma unroll
    for (int mf = 0; mf < 4; mf++) {
        const int r = wm * 64 + mf * 16 + lr;
        #pragma unroll
        for (int nf = 0; nf < 4; nf++) {
            const int c = wn * 32 + nf * 8 + 2 * lc;
            *(float2*)&Cs[r * CSTR + c]       = make_float2(acc[mf][nf][0], acc[mf][nf][1]);
            *(float2*)&Cs[(r + 8) * CSTR + c] = make_float2(acc[mf][nf][2], acc[mf][nf][3]);
        }
    }
    __syncthreads();

    {
        const int rr = tid >> 1;
        const int half = tid & 1;
        const int r = m0 + rr;
        const int g = 3 * r + (n0 >> 10);
        const int u = g >> 11, t = g & 2047;
        const int d0 = (n0 & 1023) >> 4;
        const bool isV = ((u >> 1) == 2);
        #pragma unroll
        for (int j = 0; j < 8; j++) {
            const int hh = half * 8 + j;
            float o[8];
            #pragma unroll
            for (int e = 0; e < 8; e++)
                o[e] = Cs[rr * CSTR + hh + 16 * e] + __ldg(&bias[n0 + hh + 16 * e]);
            float* base = g_qkv + (size_t)(u * 16 + hh) * (SEQ * HS);
            if (isV) {
                // V stored d-major: [d][t]
                #pragma unroll
                for (int e = 0; e < 8; e++)
                    base[(size_t)(d0 + e) * SEQ + t] = o[e];
            } else {
                float* dst = base + (size_t)t * HS + d0;
                *(float4*)dst       = make_float4(o[0], o[1], o[2], o[3]);
                *(float4*)(dst + 4) = make_float4(o[4], o[5], o[6], o[7]);
            }
        }
    }
}

// ---------------------------------------------------------------------------
// Kernel 2: flash attention via mma.sync bf16 m16n8k16, split-2 precision.
// BR=128 rows/CTA, 8 warps (16 rows each), BC=64 keys per tile.
// SMEM (uint32 = bf16x2 pairs along k):
//   Qhi/Qlo [128][32], Khi/Klo [64 t][32 d-pairs], Vhi/Vlo [64 d][32 t-pairs]
//   Total 16384 u32 = 64KB -> 2 CTAs/SM.
// P@V reuses the QK D-fragment pairs directly as A-fragments (no shuffles).
// ---------------------------------------------------------------------------
#define ATT_SMEM_BYTES (16384 * 4)

__global__ void __launch_bounds__(256, 2) attn_mma(float* __restrict__ out) {
    extern __shared__ uint32_t sm[];
    uint32_t* Qhi = sm;                 // 4096
    uint32_t* Qlo = sm + 4096;          // 4096
    uint32_t* Khi = sm + 8192;          // 2048
    uint32_t* Klo = sm + 10240;         // 2048
    uint32_t* Vhi = sm + 12288;         // 2048
    uint32_t* Vlo = sm + 14336;         // 2048

    const int tid  = threadIdx.x;
    const int lane = tid & 31;
    const int w    = tid >> 5;          // warp 0..7, rows [16w,16w+16)
    const int lr   = lane >> 2, lc = lane & 3;
    const int qtile = (int)(gridDim.x - 1) - (int)blockIdx.x;  // long CTAs first
    const int h = blockIdx.y, b = blockIdx.z;
    const int q0 = qtile * 128;

    const float* qg  = g_qkv + (size_t)(b * 16 + h) * (SEQ * HS);        // [t][d]
    const float* kg  = g_qkv + (size_t)((2 + b) * 16 + h) * (SEQ * HS);  // [t][d]
    const float* vtg = g_qkv + (size_t)((4 + b) * 16 + h) * (SEQ * HS);  // [d][t]

    // ---- Load Q tile (scaled by 2^-3, exact), split-2 into bf16x2 pairs ----
    #pragma unroll
    for (int i = 0; i < 8; i++) {
        int f = tid + i * 256;
        int r = f >> 4, d4 = (f & 15) << 2;
        float4 v = *(const float4*)(qg + (size_t)(q0 + r) * HS + d4);
        v.x *= 0.125f; v.y *= 0.125f; v.z *= 0.125f; v.w *= 0.125f;
        uint32_t idx = r * 32 + (((uint32_t)d4 >> 1) ^ (((uint32_t)(r & 7)) << 2));
        uint2 hi, lo;
        split_bf2(v.x, v.y, hi.x, lo.x);
        split_bf2(v.z, v.w, hi.y, lo.y);
        *(uint2*)&Qhi[idx] = hi;
        *(uint2*)&Qlo[idx] = lo;
    }

    float oacc[8][4];
    #pragma unroll
    for (int j = 0; j < 8; j++)
        #pragma unroll
        for (int k = 0; k < 4; k++) oacc[j][k] = 0.0f;
    float m0 = -1e30f, m1 = -1e30f, l0 = 0.0f, l1 = 0.0f;

    // Per-thread K/V staging: quad of 4 fp32 -> 2 bf16x2 pairs
    const int st_r  = tid >> 4;               // 0..15 (+16i)
    const int st_c4 = (tid & 15) << 2;        // 0..60
    const uint32_t xmask = (uint32_t)(lane >> 2 & 7) << 2;  // = lr<<2 (frag swizzle)

    const int nkt = 2 * qtile + 2;
    for (int kt = 0; kt < nkt; kt++) {
        const int k0g = kt * 64;

        // ---- K quad: LDG issued pre-sync ----
        float4 kreg[4];
        uint32_t kidx[4];
        #pragma unroll
        for (int i = 0; i < 4; i++) {
            int rr = st_r + i * 16;
            kreg[i] = *(const float4*)(kg + (size_t)(k0g + rr) * HS + st_c4);
            kidx[i] = rr * 32 + (((uint32_t)st_c4 >> 1) ^ (((uint32_t)(rr & 7)) << 2));
        }
        __syncthreads();   // prev-tile consumers done
        #pragma unroll
        for (int i = 0; i < 4; i++) {
            uint2 hi, lo;
            split_bf2(kreg[i].x, kreg[i].y, hi.x, lo.x);
            split_bf2(kreg[i].z, kreg[i].w, hi.y, lo.y);
            *(uint2*)&Khi[kidx[i]] = hi;
            *(uint2*)&Klo[kidx[i]] = lo;
        }
        // ---- V^T quad ----
        float4 vreg[4];
        #pragma unroll
        for (int i = 0; i < 4; i++)
            vreg[i] = *(const float4*)(vtg + (size_t)(st_r + i * 16) * SEQ + k0g + st_c4);
        #pragma unroll
        for (int i = 0; i < 4; i++) {
            uint2 hi, lo;
            split_bf2(vreg[i].x, vreg[i].y, hi.x, lo.x);
            split_bf2(vreg[i].z, vreg[i].w, hi.y, lo.y);
            *(uint2*)&Vhi[kidx[i]] = hi;
            *(uint2*)&Vlo[kidx[i]] = lo;
        }
        __syncthreads();   // tiles visible

        // Full-skip: all cols of this tile above all rows of this warp
        if (k0g > q0 + 16 * w + 15) continue;

        // ---- S = Q K^T (bf16 split-2, 3-term) ----
        float sacc[8][4];
        #pragma unroll
        for (int j = 0; j < 8; j++)
            #pragma unroll
            for (int k = 0; k < 4; k++) sacc[j][k] = 0.0f;

        const int r = 16 * w + lr;
        const uint32_t qbase = r * 32;
        #pragma unroll
        for (int ks = 0; ks < 4; ks++) {
            const uint32_t c1x = ((uint32_t)(8 * ks + lc)) ^ xmask;
            const uint32_t c2x = ((uint32_t)(8 * ks + lc + 4)) ^ xmask;
            uint32_t ahi[4], alo[4];
            ahi[0] = Qhi[qbase + c1x];       alo[0] = Qlo[qbase + c1x];
            ahi[1] = Qhi[qbase + 256 + c1x]; alo[1] = Qlo[qbase + 256 + c1x];
            ahi[2] = Qhi[qbase + c2x];       alo[2] = Qlo[qbase + c2x];
            ahi[3] = Qhi[qbase + 256 + c2x]; alo[3] = Qlo[qbase + 256 + c2x];
            #pragma unroll
            for (int j = 0; j < 8; j++) {
                const uint32_t nb = (uint32_t)(8 * j + lr) * 32;
                uint32_t bh[2] = { Khi[nb + c1x], Khi[nb + c2x] };
                mma_bf16(sacc[j], ahi, bh);
                mma_bf16(sacc[j], alo, bh);
                uint32_t bl[2] = { Klo[nb + c1x], Klo[nb + c2x] };
                mma_bf16(sacc[j], ahi, bl);
            }
        }

        // ---- Causal mask (only near diagonal) ----
        const int row0 = q0 + 16 * w + lr;
        if (k0g + 63 > q0 + 16 * w) {
            #pragma unroll
            for (int j = 0; j < 8; j++) {
                const int c0 = k0g + 8 * j + 2 * lc;
                if (c0 > row0)         sacc[j][0] = -1e30f;
                if (c0 + 1 > row0)     sacc[j][1] = -1e30f;
                if (c0 > row0 + 8)     sacc[j][2] = -1e30f;
                if (c0 + 1 > row0 + 8) sacc[j][3] = -1e30f;
            }
        }

        // ---- Online softmax (registers + quad shuffles) ----
        float ml0 = -1e30f, ml1 = -1e30f;
        #pragma unroll
        for (int j = 0; j < 8; j++) {
            ml0 = fmaxf(ml0, fmaxf(sacc[j][0], sacc[j][1]));
            ml1 = fmaxf(ml1, fmaxf(sacc[j][2], sacc[j][3]));
        }
        ml0 = fmaxf(ml0, __shfl_xor_sync(0xffffffffu, ml0, 1));
        ml0 = fmaxf(ml0, __shfl_xor_sync(0xffffffffu, ml0, 2));
        ml1 = fmaxf(ml1, __shfl_xor_sync(0xffffffffu, ml1, 1));
        ml1 = fmaxf(ml1, __shfl_xor_sync(0xffffffffu, ml1, 2));

        const float mn0 = fmaxf(m0, ml0), mn1 = fmaxf(m1, ml1);
        const float fac0 = __expf(m0 - mn0), fac1 = __expf(m1 - mn1);
        float ls0 = 0.0f, ls1 = 0.0f;
        #pragma unroll
        for (int j = 0; j < 8; j++) {
            float p0 = __expf(sacc[j][0] - mn0);
            float p1 = __expf(sacc[j][1] - mn0);
            float p2 = __expf(sacc[j][2] - mn1);
            float p3 = __expf(sacc[j][3] - mn1);
            sacc[j][0] = p0; sacc[j][1] = p1; sacc[j][2] = p2; sacc[j][3] = p3;
            ls0 += p0 + p1; ls1 += p2 + p3;
        }
        ls0 += __shfl_xor_sync(0xffffffffu, ls0, 1);
        ls0 += __shfl_xor_sync(0xffffffffu, ls0, 2);
        ls1 += __shfl_xor_sync(0xffffffffu, ls1, 1);
        ls1 += __shfl_xor_sync(0xffffffffu, ls1, 2);
        l0 = l0 * fac0 + ls0;
        l1 = l1 * fac1 + ls1;
        m0 = mn0; m1 = mn1;

        #pragma unroll
        for (int j = 0; j < 8; j++) {
            oacc[j][0] *= fac0; oacc[j][1] *= fac0;
            oacc[j][2] *= fac1; oacc[j][3] *= fac1;
        }

        // ---- O += P V : D-frag pairs ARE the A-frag pairs (no shuffles) ----
        #pragma unroll
        for (int ks = 0; ks < 4; ks++) {
            uint32_t phi[4], plo[4];
            split_bf2(sacc[2 * ks][0],     sacc[2 * ks][1],     phi[0], plo[0]);
            split_bf2(sacc[2 * ks][2],     sacc[2 * ks][3],     phi[1], plo[1]);
            split_bf2(sacc[2 * ks + 1][0], sacc[2 * ks + 1][1], phi[2], plo[2]);
            split_bf2(sacc[2 * ks + 1][2], sacc[2 * ks + 1][3], phi[3], plo[3]);
            const uint32_t c1x = ((uint32_t)(8 * ks + lc)) ^ xmask;
            const uint32_t c2x = ((uint32_t)(8 * ks + lc + 4)) ^ xmask;
            #pragma unroll
            for (int j = 0; j < 8; j++) {
                const uint32_t nb = (uint32_t)(8 * j + lr) * 32;
                uint32_t bvh[2] = { Vhi[nb + c1x], Vhi[nb + c2x] };
                mma_bf16(oacc[j], phi, bvh);
                mma_bf16(oacc[j], plo, bvh);
                uint32_t bvl[2] = { Vlo[nb + c1x], Vlo[nb + c2x] };
                mma_bf16(oacc[j], phi, bvl);
            }
        }
    }

    // ---- Write O, normalized ----
    const float inv0 = 1.0f / l0, inv1 = 1.0f / l1;
    const int row = q0 + 16 * w + lr;
    float* ob0 = out + ((size_t)(b * SEQ + row)) * HIDDEN + h * HS;
    float* ob1 = out + ((size_t)(b * SEQ + row + 8)) * HIDDEN + h * HS;
    #pragma unroll
    for (int j = 0; j < 8; j++) {
        const int c = 8 * j + 2 * lc;
        *(float2*)(ob0 + c) = make_float2(oacc[j][0] * inv0, oacc[j][1] * inv0);
        *(float2*)(ob1 + c) = make_float2(oacc[j][2] * inv1, oacc[j][3] * inv1);
    }
}

// ---------------------------------------------------------------------------
// Launch
// ---------------------------------------------------------------------------
extern "C" void kernel_launch(void* const* d_in, const int* in_sizes, int n_in,
                              void* d_out, int out_size) {
    const float* x    = (const float*)d_in[0];
    const float* W    = (const float*)d_in[1];
    const float* bias = (const float*)d_in[2];
    float* out = (float*)d_out;

    cudaFuncSetAttribute(qkv_gemm_tc,
                         cudaFuncAttributeMaxDynamicSharedMemorySize,
                         GEMM_SMEM_BYTES);
    qkv_gemm_tc<<<dim3(N_COLS / 128, M_ROWS / 128), 256, GEMM_SMEM_BYTES>>>(
        x, W, bias);

    cudaFuncSetAttribute(attn_mma,
                         cudaFuncAttributeMaxDynamicSharedMemorySize,
                         ATT_SMEM_BYTES);
    attn_mma<<<dim3(SEQ / 128, N_HEADS, BATCH), 256, ATT_SMEM_BYTES>>>(out);
}